// round 1
// baseline (speedup 1.0000x reference)
#include <cuda_runtime.h>

#define BATCH   256
#define IN_DIM  65536
#define OUT_DIM 65536

// ---------------- device scratch (no allocation allowed) ----------------
__device__ float4 g_coef[OUT_DIM];          // 1 MB  : per-neuron bilinear coeffs
__device__ float  g_xt[(size_t)IN_DIM * BATCH]; // 64 MB : x transposed [IN_DIM][B]
__device__ int    g_idx[2 * OUT_DIM];       // 512 KB: normalized int32 indices
__device__ int    g_is64;

// ---------------- dtype detection for indices (int64 vs int32) ----------
__global__ void detect_kernel(const void* idx_raw) {
    if (threadIdx.x == 0) {
        const long long* p = (const long long*)idx_raw;
        int is64 = 1;
        #pragma unroll 1
        for (int j = 0; j < 64; j++) {
            long long v = p[j];            // safe: 64*8 bytes << min buffer size
            if (v < 0 || v >= IN_DIM) { is64 = 0; break; }
        }
        g_is64 = is64;
    }
}

__global__ void convert_idx_kernel(const void* idx_raw) {
    int i = blockIdx.x * blockDim.x + threadIdx.x;
    if (i < 2 * OUT_DIM) {
        if (g_is64) g_idx[i] = (int)((const long long*)idx_raw)[i];
        else        g_idx[i] = ((const int*)idx_raw)[i];
    }
}

// ---------------- softmax -> bilinear coefficients ----------------------
// out = w0 + w1*a + w2*b + w3*a*b, derived from the 16 ops' (c0,c1,c2,c3).
__global__ void coef_kernel(const float* __restrict__ w) {
    int o = blockIdx.x * blockDim.x + threadIdx.x;
    if (o >= OUT_DIM) return;
    float p[16];
    const float4* w4 = (const float4*)(w + (size_t)o * 16);
    float4 q0 = w4[0], q1 = w4[1], q2 = w4[2], q3 = w4[3];
    p[0]=q0.x; p[1]=q0.y; p[2]=q0.z; p[3]=q0.w;
    p[4]=q1.x; p[5]=q1.y; p[6]=q1.z; p[7]=q1.w;
    p[8]=q2.x; p[9]=q2.y; p[10]=q2.z; p[11]=q2.w;
    p[12]=q3.x; p[13]=q3.y; p[14]=q3.z; p[15]=q3.w;
    float m = p[0];
    #pragma unroll
    for (int i = 1; i < 16; i++) m = fmaxf(m, p[i]);
    float s = 0.f;
    #pragma unroll
    for (int i = 0; i < 16; i++) { p[i] = __expf(p[i] - m); s += p[i]; }
    float inv = 1.0f / s;
    #pragma unroll
    for (int i = 0; i < 16; i++) p[i] *= inv;

    float4 c;
    c.x = p[8]+p[9]+p[10]+p[11]+p[12]+p[13]+p[14]+p[15];                 // const
    c.y = p[2]+p[3]+p[6]+p[7]-p[8]-p[9]-p[12]-p[13];                     // * a
    c.z = p[4]+p[5]+p[6]+p[7]-p[8]-p[9]-p[10]-p[11];                     // * b
    c.w = p[1]-p[2]-p[4]-2.f*p[6]-p[7]+p[8]+2.f*p[9]+p[11]+p[13]-p[14]; // * ab
    g_coef[o] = c;
}

// ---------------- transpose x[B][IN] -> xt[IN][B] -----------------------
__global__ void transpose_kernel(const float* __restrict__ x) {
    __shared__ float t[32][33];
    int i0 = blockIdx.x * 32;
    int b0 = blockIdx.y * 32;
    int tx = threadIdx.x, ty = threadIdx.y;   // block (32, 8)
    #pragma unroll
    for (int r = 0; r < 32; r += 8)
        t[ty + r][tx] = x[(size_t)(b0 + ty + r) * IN_DIM + i0 + tx];
    __syncthreads();
    #pragma unroll
    for (int r = 0; r < 32; r += 8)
        g_xt[(size_t)(i0 + ty + r) * BATCH + b0 + tx] = t[tx][ty + r];
}

// ---------------- main: one warp per output neuron ----------------------
// Block = 32 warps = 32 neurons. Warp w gathers rows xt[i0],xt[i1] (1KB each,
// coalesced float4), computes bilinear combo, stages in padded smem, then the
// block writes out[b, o_tile] with 128B-coalesced stores.
__global__ __launch_bounds__(1024, 2) void logic_main_kernel(float* __restrict__ out) {
    __shared__ float s[BATCH * 33];           // 33792 B, +1 pad per b-row
    int w = threadIdx.x >> 5;                 // warp id = local neuron
    int l = threadIdx.x & 31;
    int o = blockIdx.x * 32 + w;

    int i0 = g_idx[o];
    int i1 = g_idx[OUT_DIM + o];
    float4 c = g_coef[o];

    const float4* r0 = (const float4*)(g_xt + (size_t)i0 * BATCH);
    const float4* r1 = (const float4*)(g_xt + (size_t)i1 * BATCH);

    #pragma unroll
    for (int ch = 0; ch < 2; ch++) {
        int j = ch * 32 + l;                  // float4 index: b = 4j..4j+3
        float4 a  = r0[j];
        float4 bb = r1[j];
        int bbase = j * 4;
        s[(bbase + 0) * 33 + w] = fmaf(fmaf(c.w, bb.x, c.y), a.x, fmaf(c.z, bb.x, c.x));
        s[(bbase + 1) * 33 + w] = fmaf(fmaf(c.w, bb.y, c.y), a.y, fmaf(c.z, bb.y, c.x));
        s[(bbase + 2) * 33 + w] = fmaf(fmaf(c.w, bb.z, c.y), a.z, fmaf(c.z, bb.z, c.x));
        s[(bbase + 3) * 33 + w] = fmaf(fmaf(c.w, bb.w, c.y), a.w, fmaf(c.z, bb.w, c.x));
    }
    __syncthreads();

    int ob = blockIdx.x * 32;
    #pragma unroll
    for (int j = 0; j < 8; j++) {
        int b = w * 8 + j;                    // warp w owns batch rows w*8..w*8+7
        out[(size_t)b * OUT_DIM + ob + l] = s[b * 33 + l];
    }
}

// ---------------- launch ------------------------------------------------
extern "C" void kernel_launch(void* const* d_in, const int* in_sizes, int n_in,
                              void* d_out, int out_size) {
    const float* x   = (const float*)d_in[0];
    const float* wts = (const float*)d_in[1];
    const void*  idx = d_in[2];
    float* out = (float*)d_out;

    detect_kernel<<<1, 32>>>(idx);
    convert_idx_kernel<<<(2 * OUT_DIM + 255) / 256, 256>>>(idx);
    coef_kernel<<<OUT_DIM / 256, 256>>>(wts);
    transpose_kernel<<<dim3(IN_DIM / 32, BATCH / 32), dim3(32, 8)>>>(x);
    logic_main_kernel<<<OUT_DIM / 32, 1024>>>(out);
}

// round 2
// speedup vs baseline: 1.2613x; 1.2613x over previous
#include <cuda_runtime.h>
#include <cuda_fp16.h>

#define BATCH   256
#define IN_DIM  65536
#define OUT_DIM 65536

// ---------------- device scratch (no allocation allowed) ----------------
__device__ float4 g_coef[OUT_DIM];                         // 1 MB
__device__ __align__(16) __half g_xth[(size_t)IN_DIM * BATCH]; // 32 MB: x^T as fp16 [IN][B]
__device__ int    g_idx[2 * OUT_DIM];                      // 512 KB
__device__ int    g_is64;

// ---------------- dtype detection for indices (int64 vs int32) ----------
__global__ void detect_kernel(const void* idx_raw) {
    if (threadIdx.x == 0) {
        const long long* p = (const long long*)idx_raw;
        int is64 = 1;
        #pragma unroll 1
        for (int j = 0; j < 64; j++) {
            long long v = p[j];
            if (v < 0 || v >= IN_DIM) { is64 = 0; break; }
        }
        g_is64 = is64;
    }
}

__global__ void convert_idx_kernel(const void* idx_raw) {
    int i = blockIdx.x * blockDim.x + threadIdx.x;
    if (i < 2 * OUT_DIM) {
        if (g_is64) g_idx[i] = (int)((const long long*)idx_raw)[i];
        else        g_idx[i] = ((const int*)idx_raw)[i];
    }
}

// ---------------- softmax -> bilinear coefficients ----------------------
// out = c0 + c1*a + c2*b + c3*a*b (exact collapse of the 16 relaxations)
__global__ void coef_kernel(const float* __restrict__ w) {
    int o = blockIdx.x * blockDim.x + threadIdx.x;
    if (o >= OUT_DIM) return;
    float p[16];
    const float4* w4 = (const float4*)(w + (size_t)o * 16);
    float4 q0 = w4[0], q1 = w4[1], q2 = w4[2], q3 = w4[3];
    p[0]=q0.x; p[1]=q0.y; p[2]=q0.z; p[3]=q0.w;
    p[4]=q1.x; p[5]=q1.y; p[6]=q1.z; p[7]=q1.w;
    p[8]=q2.x; p[9]=q2.y; p[10]=q2.z; p[11]=q2.w;
    p[12]=q3.x; p[13]=q3.y; p[14]=q3.z; p[15]=q3.w;
    float m = p[0];
    #pragma unroll
    for (int i = 1; i < 16; i++) m = fmaxf(m, p[i]);
    float s = 0.f;
    #pragma unroll
    for (int i = 0; i < 16; i++) { p[i] = __expf(p[i] - m); s += p[i]; }
    float inv = 1.0f / s;
    #pragma unroll
    for (int i = 0; i < 16; i++) p[i] *= inv;

    float4 c;
    c.x = p[8]+p[9]+p[10]+p[11]+p[12]+p[13]+p[14]+p[15];
    c.y = p[2]+p[3]+p[6]+p[7]-p[8]-p[9]-p[12]-p[13];
    c.z = p[4]+p[5]+p[6]+p[7]-p[8]-p[9]-p[10]-p[11];
    c.w = p[1]-p[2]-p[4]-2.f*p[6]-p[7]+p[8]+2.f*p[9]+p[11]+p[13]-p[14];
    g_coef[o] = c;
}

// ---------------- transpose x[B][IN] (f32) -> g_xth[IN][B] (f16) --------
// Tile: 64 batches x 32 inputs. Block (8,32) = 256 threads.
// Loads: 2x float4 per thread (128B-coalesced). Smem 64x33 conflict-free.
// Stores: one uint4 (8 halves) per thread -> 128B-coalesced rows of xt.
__global__ void transpose_kernel(const float* __restrict__ x) {
    __shared__ float t[64][33];
    int i0 = blockIdx.x * 32;
    int b0 = blockIdx.y * 64;
    int tx = threadIdx.x;   // 0..7
    int ty = threadIdx.y;   // 0..31

    const float4* s0 = (const float4*)(x + (size_t)(b0 + ty)      * IN_DIM + i0);
    const float4* s1 = (const float4*)(x + (size_t)(b0 + 32 + ty) * IN_DIM + i0);
    float4 v0 = s0[tx];
    float4 v1 = s1[tx];
    t[ty     ][tx*4+0]=v0.x; t[ty     ][tx*4+1]=v0.y; t[ty     ][tx*4+2]=v0.z; t[ty     ][tx*4+3]=v0.w;
    t[ty + 32][tx*4+0]=v1.x; t[ty + 32][tx*4+1]=v1.y; t[ty + 32][tx*4+2]=v1.z; t[ty + 32][tx*4+3]=v1.w;
    __syncthreads();

    // thread (tx,ty): row i = i0+ty, batches b0+8tx..+7
    union { uint4 u; __half2 h[4]; } pk;
    #pragma unroll
    for (int k = 0; k < 4; k++)
        pk.h[k] = __floats2half2_rn(t[8*tx + 2*k][ty], t[8*tx + 2*k + 1][ty]);
    *(uint4*)(g_xth + (size_t)(i0 + ty) * BATCH + b0 + 8*tx) = pk.u;
}

// ---------------- main: one warp per output neuron ----------------------
// Warp w: neuron o. ONE uint4 warp-load fetches the whole 512B fp16 row.
// Lane l owns batches 8l..8l+7. Staging smem uses an additive swizzle that
// is bank-conflict-free on both store (compute) and read (coalesced out).
#define SWZ(b) ((20 * (((b) >> 2) & 7) + (((b) >> 5) & 7)) & 31)

__global__ __launch_bounds__(1024, 2) void logic_main_kernel(float* __restrict__ out) {
    __shared__ float s[BATCH * 32];           // 32 KB
    int w = threadIdx.x >> 5;
    int l = threadIdx.x & 31;
    int o = blockIdx.x * 32 + w;

    int i0 = g_idx[o];
    int i1 = g_idx[OUT_DIM + o];
    float4 c = g_coef[o];

    uint4 ua = ((const uint4*)(g_xth + (size_t)i0 * BATCH))[l];
    uint4 ub = ((const uint4*)(g_xth + (size_t)i1 * BATCH))[l];
    union { uint4 u; __half2 h[4]; } A, Bv;
    A.u = ua; Bv.u = ub;

    int bbase = 8 * l;
    #pragma unroll
    for (int k2 = 0; k2 < 4; k2++) {
        float2 a = __half22float2(A.h[k2]);
        float2 b = __half22float2(Bv.h[k2]);
        float v0 = fmaf(fmaf(c.w, b.x, c.y), a.x, fmaf(c.z, b.x, c.x));
        float v1 = fmaf(fmaf(c.w, b.y, c.y), a.y, fmaf(c.z, b.y, c.x));
        int b0i = bbase + 2 * k2;
        int b1i = b0i + 1;
        s[b0i * 32 + ((w + SWZ(b0i)) & 31)] = v0;
        s[b1i * 32 + ((w + SWZ(b1i)) & 31)] = v1;
    }
    __syncthreads();

    int ob = blockIdx.x * 32;
    #pragma unroll
    for (int j = 0; j < 8; j++) {
        int b = w * 8 + j;
        out[(size_t)b * OUT_DIM + ob + l] = s[b * 32 + ((l + SWZ(b)) & 31)];
    }
}

// ---------------- launch ------------------------------------------------
extern "C" void kernel_launch(void* const* d_in, const int* in_sizes, int n_in,
                              void* d_out, int out_size) {
    const float* x   = (const float*)d_in[0];
    const float* wts = (const float*)d_in[1];
    const void*  idx = d_in[2];
    float* out = (float*)d_out;

    detect_kernel<<<1, 32>>>(idx);
    convert_idx_kernel<<<(2 * OUT_DIM + 255) / 256, 256>>>(idx);
    coef_kernel<<<OUT_DIM / 256, 256>>>(wts);
    transpose_kernel<<<dim3(IN_DIM / 32, BATCH / 64), dim3(8, 32)>>>(x);
    logic_main_kernel<<<OUT_DIM / 32, 1024>>>(out);
}

// round 3
// speedup vs baseline: 1.3852x; 1.0982x over previous
#include <cuda_runtime.h>
#include <cuda_fp16.h>

#define BATCH   256
#define IN_DIM  65536
#define OUT_DIM 65536

// ---------------- device scratch (no allocation allowed) ----------------
__device__ float4 g_coef[OUT_DIM];                             // 1 MB
__device__ __align__(16) __half g_xth[(size_t)IN_DIM * BATCH]; // 32 MB: x^T fp16 [IN][B]
__device__ int    g_idx[2 * OUT_DIM];                          // 512 KB
__device__ int    g_is64;

// ---------------- dtype detection for indices (int64 vs int32) ----------
__global__ void detect_kernel(const void* idx_raw) {
    if (threadIdx.x == 0) {
        const long long* p = (const long long*)idx_raw;
        int is64 = 1;
        #pragma unroll 1
        for (int j = 0; j < 64; j++) {
            long long v = p[j];
            if (v < 0 || v >= IN_DIM) { is64 = 0; break; }
        }
        g_is64 = is64;
    }
}

__global__ void convert_idx_kernel(const void* idx_raw) {
    int i = blockIdx.x * blockDim.x + threadIdx.x;
    if (i < 2 * OUT_DIM) {
        if (g_is64) g_idx[i] = (int)((const long long*)idx_raw)[i];
        else        g_idx[i] = ((const int*)idx_raw)[i];
    }
}

// ---------------- softmax -> bilinear coefficients ----------------------
// out = c0 + c1*a + c2*b + c3*a*b (exact collapse of the 16 relaxations)
__global__ void coef_kernel(const float* __restrict__ w) {
    int o = blockIdx.x * blockDim.x + threadIdx.x;
    if (o >= OUT_DIM) return;
    float p[16];
    const float4* w4 = (const float4*)(w + (size_t)o * 16);
    float4 q0 = w4[0], q1 = w4[1], q2 = w4[2], q3 = w4[3];
    p[0]=q0.x; p[1]=q0.y; p[2]=q0.z; p[3]=q0.w;
    p[4]=q1.x; p[5]=q1.y; p[6]=q1.z; p[7]=q1.w;
    p[8]=q2.x; p[9]=q2.y; p[10]=q2.z; p[11]=q2.w;
    p[12]=q3.x; p[13]=q3.y; p[14]=q3.z; p[15]=q3.w;
    float m = p[0];
    #pragma unroll
    for (int i = 1; i < 16; i++) m = fmaxf(m, p[i]);
    float s = 0.f;
    #pragma unroll
    for (int i = 0; i < 16; i++) { p[i] = __expf(p[i] - m); s += p[i]; }
    float inv = 1.0f / s;
    #pragma unroll
    for (int i = 0; i < 16; i++) p[i] *= inv;

    float4 c;
    c.x = p[8]+p[9]+p[10]+p[11]+p[12]+p[13]+p[14]+p[15];
    c.y = p[2]+p[3]+p[6]+p[7]-p[8]-p[9]-p[12]-p[13];
    c.z = p[4]+p[5]+p[6]+p[7]-p[8]-p[9]-p[10]-p[11];
    c.w = p[1]-p[2]-p[4]-2.f*p[6]-p[7]+p[8]+2.f*p[9]+p[11]+p[13]-p[14];
    g_coef[o] = c;
}

// ---------------- transpose x[B][IN] (f32) -> g_xth[IN][B] (f16) --------
// Tile: 64 batches x 64 inputs per block (2 input sub-tiles). Block (8,32).
// 4 float4 loads per thread in flight before the barrier (MLP=4).
__global__ void transpose_kernel(const float* __restrict__ x) {
    __shared__ float t[2][64][33];
    int i0 = blockIdx.x * 64;
    int b0 = blockIdx.y * 64;
    int tx = threadIdx.x;   // 0..7
    int ty = threadIdx.y;   // 0..31

    const float4* r0 = (const float4*)(x + (size_t)(b0 + ty)      * IN_DIM + i0);
    const float4* r1 = (const float4*)(x + (size_t)(b0 + 32 + ty) * IN_DIM + i0);
    float4 v00 = r0[tx];
    float4 v01 = r0[tx + 8];
    float4 v10 = r1[tx];
    float4 v11 = r1[tx + 8];

    t[0][ty   ][tx*4+0]=v00.x; t[0][ty   ][tx*4+1]=v00.y; t[0][ty   ][tx*4+2]=v00.z; t[0][ty   ][tx*4+3]=v00.w;
    t[1][ty   ][tx*4+0]=v01.x; t[1][ty   ][tx*4+1]=v01.y; t[1][ty   ][tx*4+2]=v01.z; t[1][ty   ][tx*4+3]=v01.w;
    t[0][ty+32][tx*4+0]=v10.x; t[0][ty+32][tx*4+1]=v10.y; t[0][ty+32][tx*4+2]=v10.z; t[0][ty+32][tx*4+3]=v10.w;
    t[1][ty+32][tx*4+0]=v11.x; t[1][ty+32][tx*4+1]=v11.y; t[1][ty+32][tx*4+2]=v11.z; t[1][ty+32][tx*4+3]=v11.w;
    __syncthreads();

    #pragma unroll
    for (int h = 0; h < 2; h++) {
        union { uint4 u; __half2 hh[4]; } pk;
        #pragma unroll
        for (int k = 0; k < 4; k++)
            pk.hh[k] = __floats2half2_rn(t[h][8*tx + 2*k][ty], t[h][8*tx + 2*k + 1][ty]);
        *(uint4*)(g_xth + (size_t)(i0 + 32*h + ty) * BATCH + b0 + 8*tx) = pk.u;
    }
}

// ---------------- main: 8 warps x 4 neurons per 256-thread block --------
// Each warp issues 8 independent uint4 loads (full 512B fp16 rows) before
// computing. Staging smem uses the additive swizzle (conflict-free on both
// the scalar store side and the coalesced read side).
#define SWZ(b) ((20 * (((b) >> 2) & 7) + (((b) >> 5) & 7)) & 31)

__global__ __launch_bounds__(256, 4) void logic_main_kernel(float* __restrict__ out) {
    __shared__ float s[BATCH * 32];           // 32 KB
    int tid = threadIdx.x;
    int w = tid >> 5;                         // 0..7
    int l = tid & 31;
    int ob = blockIdx.x * 32;
    int n0 = w * 4;                           // this warp's 4 local neurons

    // gather indices + issue all 8 row loads up front (MLP = 8)
    int ia[4], ib[4];
    #pragma unroll
    for (int c = 0; c < 4; c++) {
        int o = ob + n0 + c;
        ia[c] = g_idx[o];
        ib[c] = g_idx[OUT_DIM + o];
    }
    uint4 va[4], vb[4];
    #pragma unroll
    for (int c = 0; c < 4; c++) {
        va[c] = ((const uint4*)(g_xth + (size_t)ia[c] * BATCH))[l];
        vb[c] = ((const uint4*)(g_xth + (size_t)ib[c] * BATCH))[l];
    }

    #pragma unroll
    for (int c = 0; c < 4; c++) {
        float4 cf = g_coef[ob + n0 + c];
        union { uint4 u; __half2 h[4]; } A, Bv;
        A.u = va[c]; Bv.u = vb[c];
        int n = n0 + c;
        int bbase = 8 * l;
        #pragma unroll
        for (int k2 = 0; k2 < 4; k2++) {
            float2 a = __half22float2(A.h[k2]);
            float2 b = __half22float2(Bv.h[k2]);
            float v0 = fmaf(fmaf(cf.w, b.x, cf.y), a.x, fmaf(cf.z, b.x, cf.x));
            float v1 = fmaf(fmaf(cf.w, b.y, cf.y), a.y, fmaf(cf.z, b.y, cf.x));
            int b0i = bbase + 2 * k2;
            int b1i = b0i + 1;
            s[b0i * 32 + ((n + SWZ(b0i)) & 31)] = v0;
            s[b1i * 32 + ((n + SWZ(b1i)) & 31)] = v1;
        }
    }
    __syncthreads();

    // warp w writes batch rows 32w..32w+31, 128B-coalesced per row
    #pragma unroll
    for (int j = 0; j < 32; j++) {
        int b = w * 32 + j;
        out[(size_t)b * OUT_DIM + ob + l] = s[b * 32 + ((l + SWZ(b)) & 31)];
    }
}

// ---------------- launch ------------------------------------------------
extern "C" void kernel_launch(void* const* d_in, const int* in_sizes, int n_in,
                              void* d_out, int out_size) {
    const float* x   = (const float*)d_in[0];
    const float* wts = (const float*)d_in[1];
    const void*  idx = d_in[2];
    float* out = (float*)d_out;

    detect_kernel<<<1, 32>>>(idx);
    convert_idx_kernel<<<(2 * OUT_DIM + 255) / 256, 256>>>(idx);
    coef_kernel<<<OUT_DIM / 256, 256>>>(wts);
    transpose_kernel<<<dim3(IN_DIM / 64, BATCH / 64), dim3(8, 32)>>>(x);
    logic_main_kernel<<<OUT_DIM / 32, 256>>>(out);
}

// round 4
// speedup vs baseline: 1.6390x; 1.1832x over previous
#include <cuda_runtime.h>
#include <cuda_fp16.h>

#define BATCH   256
#define IN_DIM  65536
#define OUT_DIM 65536

#define NB_T 2048   // transpose blocks: (IN/128) x (B/64) = 512*4
#define NB_C 256    // coef blocks: 65536/256
#define NB_I 512    // idx-convert blocks: 131072/256

// ---------------- device scratch (no allocation allowed) ----------------
__device__ float4 g_coef[OUT_DIM];                             // 1 MB
__device__ __align__(16) __half g_xth[(size_t)IN_DIM * BATCH]; // 32 MB: x^T fp16 [IN][B]
__device__ int    g_idx[2 * OUT_DIM];                          // 512 KB

// ---------------- fused prep: transpose + coef + idx convert ------------
__global__ __launch_bounds__(256) void prep_kernel(const float* __restrict__ x,
                                                   const float* __restrict__ wts,
                                                   const void*  __restrict__ idxraw) {
    __shared__ float t[4][64][33];            // 33792 B (transpose role only)
    int bx  = blockIdx.x;
    int tid = threadIdx.x;

    if (bx < NB_T) {
        // ---- transpose x[B][IN] f32 -> g_xth[IN][B] f16 ----
        // tile: 128 inputs x 64 batches; 8 float4 loads in flight per thread
        int it = bx & 511, bt = bx >> 9;
        int i0 = it * 128, b0 = bt * 64;
        int tx = tid & 7, ty = tid >> 3;      // (8, 32)

        const float4* r0 = (const float4*)(x + (size_t)(b0 + ty)      * IN_DIM + i0);
        const float4* r1 = (const float4*)(x + (size_t)(b0 + 32 + ty) * IN_DIM + i0);
        float4 v0[4], v1[4];
        #pragma unroll
        for (int h = 0; h < 4; h++) {
            v0[h] = __ldcs(r0 + tx + 8 * h);
            v1[h] = __ldcs(r1 + tx + 8 * h);
        }
        #pragma unroll
        for (int h = 0; h < 4; h++) {
            t[h][ty   ][tx*4+0]=v0[h].x; t[h][ty   ][tx*4+1]=v0[h].y;
            t[h][ty   ][tx*4+2]=v0[h].z; t[h][ty   ][tx*4+3]=v0[h].w;
            t[h][ty+32][tx*4+0]=v1[h].x; t[h][ty+32][tx*4+1]=v1[h].y;
            t[h][ty+32][tx*4+2]=v1[h].z; t[h][ty+32][tx*4+3]=v1[h].w;
        }
        __syncthreads();
        #pragma unroll
        for (int h = 0; h < 4; h++) {
            union { uint4 u; __half2 hh[4]; } pk;
            #pragma unroll
            for (int k = 0; k < 4; k++)
                pk.hh[k] = __floats2half2_rn(t[h][8*tx + 2*k][ty], t[h][8*tx + 2*k + 1][ty]);
            *(uint4*)(g_xth + (size_t)(i0 + 32*h + ty) * BATCH + b0 + 8*tx) = pk.u;
        }
    } else if (bx < NB_T + NB_C) {
        // ---- softmax -> bilinear coefficients ----
        int o = (bx - NB_T) * 256 + tid;
        float p[16];
        const float4* w4 = (const float4*)(wts + (size_t)o * 16);
        float4 q0 = w4[0], q1 = w4[1], q2 = w4[2], q3 = w4[3];
        p[0]=q0.x; p[1]=q0.y; p[2]=q0.z; p[3]=q0.w;
        p[4]=q1.x; p[5]=q1.y; p[6]=q1.z; p[7]=q1.w;
        p[8]=q2.x; p[9]=q2.y; p[10]=q2.z; p[11]=q2.w;
        p[12]=q3.x; p[13]=q3.y; p[14]=q3.z; p[15]=q3.w;
        float m = p[0];
        #pragma unroll
        for (int i = 1; i < 16; i++) m = fmaxf(m, p[i]);
        float s = 0.f;
        #pragma unroll
        for (int i = 0; i < 16; i++) { p[i] = __expf(p[i] - m); s += p[i]; }
        float inv = 1.0f / s;
        #pragma unroll
        for (int i = 0; i < 16; i++) p[i] *= inv;
        float4 c;
        c.x = p[8]+p[9]+p[10]+p[11]+p[12]+p[13]+p[14]+p[15];
        c.y = p[2]+p[3]+p[6]+p[7]-p[8]-p[9]-p[12]-p[13];
        c.z = p[4]+p[5]+p[6]+p[7]-p[8]-p[9]-p[10]-p[11];
        c.w = p[1]-p[2]-p[4]-2.f*p[6]-p[7]+p[8]+2.f*p[9]+p[11]+p[13]-p[14];
        g_coef[o] = c;
    } else {
        // ---- idx convert with per-block dtype detection ----
        __shared__ int s64;
        if (tid == 0) {
            const long long* p = (const long long*)idxraw;
            int is64 = 1;
            #pragma unroll 1
            for (int j = 0; j < 64; j++) {
                long long v = p[j];
                if (v < 0 || v >= IN_DIM) { is64 = 0; break; }
            }
            s64 = is64;
        }
        __syncthreads();
        int i = (bx - NB_T - NB_C) * 256 + tid;
        g_idx[i] = s64 ? (int)((const long long*)idxraw)[i]
                       : ((const int*)idxraw)[i];
    }
}

// ---------------- main: 8 warps x 4 neurons per 256-thread block --------
// Warp gathers 8 full fp16 rows (uint4/lane, MLP=8), computes the bilinear
// combo, stages through a conflict-free swizzled smem tile, writes out with
// 128B-coalesced streaming stores (evict-first: protect xt in L2).
#define SWZ(b) ((20 * (((b) >> 2) & 7) + (((b) >> 5) & 7)) & 31)

__global__ __launch_bounds__(256, 4) void logic_main_kernel(float* __restrict__ out) {
    __shared__ float s[BATCH * 32];           // 32 KB
    int tid = threadIdx.x;
    int w = tid >> 5;
    int l = tid & 31;
    int ob = blockIdx.x * 32;
    int n0 = w * 4;

    int ia[4], ib[4];
    #pragma unroll
    for (int c = 0; c < 4; c++) {
        int o = ob + n0 + c;
        ia[c] = g_idx[o];
        ib[c] = g_idx[OUT_DIM + o];
    }
    uint4 va[4], vb[4];
    #pragma unroll
    for (int c = 0; c < 4; c++) {
        va[c] = ((const uint4*)(g_xth + (size_t)ia[c] * BATCH))[l];
        vb[c] = ((const uint4*)(g_xth + (size_t)ib[c] * BATCH))[l];
    }

    #pragma unroll
    for (int c = 0; c < 4; c++) {
        float4 cf = g_coef[ob + n0 + c];
        union { uint4 u; __half2 h[4]; } A, Bv;
        A.u = va[c]; Bv.u = vb[c];
        int n = n0 + c;
        int bbase = 8 * l;
        #pragma unroll
        for (int k2 = 0; k2 < 4; k2++) {
            float2 a = __half22float2(A.h[k2]);
            float2 b = __half22float2(Bv.h[k2]);
            float v0 = fmaf(fmaf(cf.w, b.x, cf.y), a.x, fmaf(cf.z, b.x, cf.x));
            float v1 = fmaf(fmaf(cf.w, b.y, cf.y), a.y, fmaf(cf.z, b.y, cf.x));
            int b0i = bbase + 2 * k2;
            int b1i = b0i + 1;
            s[b0i * 32 + ((n + SWZ(b0i)) & 31)] = v0;
            s[b1i * 32 + ((n + SWZ(b1i)) & 31)] = v1;
        }
    }
    __syncthreads();

    #pragma unroll
    for (int j = 0; j < 32; j++) {
        int b = w * 32 + j;
        __stcs(out + (size_t)b * OUT_DIM + ob + l,
               s[b * 32 + ((l + SWZ(b)) & 31)]);
    }
}

// ---------------- launch ------------------------------------------------
extern "C" void kernel_launch(void* const* d_in, const int* in_sizes, int n_in,
                              void* d_out, int out_size) {
    const float* x   = (const float*)d_in[0];
    const float* wts = (const float*)d_in[1];
    const void*  idx = d_in[2];
    float* out = (float*)d_out;

    prep_kernel<<<NB_T + NB_C + NB_I, 256>>>(x, wts, idx);
    logic_main_kernel<<<OUT_DIM / 32, 256>>>(out);
}